// round 2
// baseline (speedup 1.0000x reference)
#include <cuda_runtime.h>

#define NN 100000
#define NE 800000
#define F  128
#define C  64
#define SCAN_T 1024
#define NSCAN  98   // ceil(100000/1024)

// ---- device scratch (no allocations allowed). float4-typed => 16B aligned. ----
__device__ float4 g_y4[NN * (C / 4)];   // projected features y = x @ W^T (25.6 MB, L2-resident)
__device__ float4 g_Wt4[F * (C / 4)];   // W transposed to [k][c], packed float4 over c
__device__ int    g_degi[NN];
__device__ int    g_cursor[NN];
__device__ int    g_off[NN + 1];
__device__ int    g_srcs[NE];           // CSR-by-dst neighbor lists
__device__ int    g_bsum[128];

// ---------------- zero counters ----------------
__global__ void k_zero() {
    int i = blockIdx.x * 256 + threadIdx.x;
    if (i < NN) { g_degi[i] = 0; g_cursor[i] = 0; }
}

// ---------------- transpose W[c][k] -> Wt[k][c] ----------------
__global__ void k_transpose(const float* __restrict__ W) {
    int i = blockIdx.x * 256 + threadIdx.x;   // i over C*F
    if (i < C * F) {
        int c = i / F, k = i % F;
        float* wt = (float*)g_Wt4;
        wt[k * C + c] = W[i];
    }
}

// ---------------- degree histogram (edges are int32!) ----------------
__global__ void k_count(const int* __restrict__ dst) {
    int e = blockIdx.x * 256 + threadIdx.x;
    if (e < NE) atomicAdd(&g_degi[dst[e]], 1);
}

// ---------------- exclusive scan (3 kernels) ----------------
__global__ void k_scan1() {
    __shared__ int sh[SCAN_T];
    int tid = threadIdx.x;
    int i = blockIdx.x * SCAN_T + tid;
    int v = (i < NN) ? g_degi[i] : 0;
    sh[tid] = v;
    __syncthreads();
    for (int o = 1; o < SCAN_T; o <<= 1) {
        int t = (tid >= o) ? sh[tid - o] : 0;
        __syncthreads();
        sh[tid] += t;
        __syncthreads();
    }
    int incl = sh[tid];
    if (i < NN) g_off[i] = incl - v;          // exclusive within block
    if (tid == SCAN_T - 1) g_bsum[blockIdx.x] = incl;
}

__global__ void k_scan2() {
    if (threadIdx.x == 0) {
        int run = 0;
        for (int i = 0; i < NSCAN; i++) { int t = g_bsum[i]; g_bsum[i] = run; run += t; }
        g_off[NN] = run;   // = NE
    }
}

__global__ void k_scan3() {
    int i = blockIdx.x * SCAN_T + threadIdx.x;
    if (i < NN) g_off[i] += g_bsum[blockIdx.x];
}

// ---------------- scatter edges into CSR slots ----------------
__global__ void k_scatter(const int* __restrict__ src,
                          const int* __restrict__ dst) {
    int e = blockIdx.x * 256 + threadIdx.x;
    if (e < NE) {
        int d = dst[e];
        int slot = atomicAdd(&g_cursor[d], 1);
        g_srcs[g_off[d] + slot] = src[e];
    }
}

// ---------------- projection GEMM: y = x @ W^T ----------------
// 32 nodes per block, 256 threads. Thread = (class-group of 4) x (2 nodes).
// W^T streamed from L1 (32 KB hot), x tile staged in smem (broadcast reads).
__global__ void __launch_bounds__(256) k_gemm(const float* __restrict__ x) {
    __shared__ float xs[32 * F];      // 16 KB
    int tid = threadIdx.x;
    int base = blockIdx.x * 32;

    const float4* xg = (const float4*)(x + (size_t)base * F);
    float4* xs4 = (float4*)xs;
    for (int i = tid; i < 32 * F / 4; i += 256) xs4[i] = xg[i];
    __syncthreads();

    int cg = tid & 15;          // class group: classes cg*4 .. cg*4+3
    int nl = tid >> 4;          // 0..15
    int n0 = nl * 2, n1 = n0 + 1;

    float4 a = {0.f, 0.f, 0.f, 0.f};
    float4 b = {0.f, 0.f, 0.f, 0.f};

    #pragma unroll 8
    for (int k = 0; k < F; k++) {
        float4 w = g_Wt4[k * 16 + cg];     // 256B contiguous per k, L1-hot
        float xa = xs[n0 * F + k];         // smem broadcast
        float xb = xs[n1 * F + k];
        a.x += xa * w.x; a.y += xa * w.y; a.z += xa * w.z; a.w += xa * w.w;
        b.x += xb * w.x; b.y += xb * w.y; b.z += xb * w.z; b.w += xb * w.w;
    }

    g_y4[(size_t)(base + n0) * 16 + cg] = a;
    g_y4[(size_t)(base + n1) * 16 + cg] = b;
}

// ---------------- gather + epilogue ----------------
// 16 threads per node (each owns a float4 of the 64-wide row). No atomics.
__global__ void __launch_bounds__(256) k_out(const float* __restrict__ bn,
                                             float* __restrict__ out) {
    int tid = threadIdx.x;
    int l  = tid & 15;
    int nl = tid >> 4;
    int v  = blockIdx.x * 16 + nl;     // 6250 * 16 == 100000, no guard needed

    float4 acc = g_y4[(size_t)v * 16 + l];   // self term

    int jb = g_off[v], je = g_off[v + 1];
    for (int j = jb; j < je; j++) {
        int s = g_srcs[j];                   // uniform across the 16-lane group
        float4 t = g_y4[(size_t)s * 16 + l]; // L2-resident gather
        acc.x += t.x; acc.y += t.y; acc.z += t.z; acc.w += t.w;
    }

    float sc = 1.0f / (float)(je - jb + 1);
    float4 bb = ((const float4*)bn)[l];
    float4 o;
    o.x = acc.x * sc + bb.x;
    o.y = acc.y * sc + bb.y;
    o.z = acc.z * sc + bb.z;
    o.w = acc.w * sc + bb.w;
    ((float4*)out)[(size_t)v * 16 + l] = o;
}

extern "C" void kernel_launch(void* const* d_in, const int* in_sizes, int n_in,
                              void* d_out, int out_size) {
    const float* x    = (const float*)d_in[0];
    const int*   esrc = (const int*)d_in[1];
    const int*   edst = (const int*)d_in[2];
    const float* W    = (const float*)d_in[3];
    const float* bn   = (const float*)d_in[4];
    float* out = (float*)d_out;

    k_zero<<<(NN + 255) / 256, 256>>>();
    k_transpose<<<(C * F + 255) / 256, 256>>>(W);
    k_count<<<(NE + 255) / 256, 256>>>(edst);
    k_scan1<<<NSCAN, SCAN_T>>>();
    k_scan2<<<1, 32>>>();
    k_scan3<<<NSCAN, SCAN_T>>>();
    k_scatter<<<(NE + 255) / 256, 256>>>(esrc, edst);
    k_gemm<<<NN / 32, 256>>>(x);
    k_out<<<NN / 16, 256>>>(bn, out);
}

// round 3
// speedup vs baseline: 1.0739x; 1.0739x over previous
#include <cuda_runtime.h>

#define NN 100000
#define NE 800000
#define F  128
#define C  64
#define SCAN_T 1024
#define NSCAN  98   // ceil(100000/1024)

typedef unsigned long long ull;

// ---- device scratch (no allocations allowed). float4-typed => 16B aligned. ----
__device__ float4 g_y4[NN * (C / 4)];   // projected features y = x @ W^T (25.6 MB, L2-resident)
__device__ float4 g_Wt4[F * (C / 4)];   // W transposed to [k][c], packed float4 over c
__device__ int    g_degi[NN];
__device__ int    g_cursor[NN];
__device__ int    g_off[NN + 1];
__device__ int    g_srcs[NE];           // CSR-by-dst neighbor lists
__device__ int    g_bsum[128];

// ---- packed f32x2 helpers (FFMA2: 2 FMA per instruction on sm_103a) ----
__device__ __forceinline__ ull ffma2(ull a, ull b, ull c) {
    ull d;
    asm("fma.rn.f32x2 %0, %1, %2, %3;" : "=l"(d) : "l"(a), "l"(b), "l"(c));
    return d;
}
__device__ __forceinline__ ull pack2(float lo, float hi) {
    ull d; asm("mov.b64 %0, {%1, %2};" : "=l"(d) : "f"(lo), "f"(hi)); return d;
}
__device__ __forceinline__ void unpack2(ull v, float& lo, float& hi) {
    asm("mov.b64 {%0, %1}, %2;" : "=f"(lo), "=f"(hi) : "l"(v));
}

// ---------------- init: zero counters + transpose W ----------------
__global__ void k_init(const float* __restrict__ W) {
    int i = blockIdx.x * 256 + threadIdx.x;
    if (i < NN) { g_degi[i] = 0; g_cursor[i] = 0; }
    if (i < C * F) {
        int c = i / F, k = i % F;
        ((float*)g_Wt4)[k * C + c] = W[i];
    }
}

// ---------------- degree histogram (edges are int32) ----------------
__global__ void k_count(const int* __restrict__ dst) {
    int e = blockIdx.x * 256 + threadIdx.x;
    if (e < NE) atomicAdd(&g_degi[dst[e]], 1);
}

// ---------------- exclusive scan (3 kernels) ----------------
__global__ void k_scan1() {
    __shared__ int sh[SCAN_T];
    int tid = threadIdx.x;
    int i = blockIdx.x * SCAN_T + tid;
    int v = (i < NN) ? g_degi[i] : 0;
    sh[tid] = v;
    __syncthreads();
    for (int o = 1; o < SCAN_T; o <<= 1) {
        int t = (tid >= o) ? sh[tid - o] : 0;
        __syncthreads();
        sh[tid] += t;
        __syncthreads();
    }
    int incl = sh[tid];
    if (i < NN) g_off[i] = incl - v;
    if (tid == SCAN_T - 1) g_bsum[blockIdx.x] = incl;
}

__global__ void k_scan2() {
    if (threadIdx.x == 0) {
        int run = 0;
        for (int i = 0; i < NSCAN; i++) { int t = g_bsum[i]; g_bsum[i] = run; run += t; }
        g_off[NN] = run;   // = NE
    }
}

__global__ void k_scan3() {
    int i = blockIdx.x * SCAN_T + threadIdx.x;
    if (i < NN) g_off[i] += g_bsum[blockIdx.x];
}

// ---------------- scatter edges into CSR slots ----------------
__global__ void k_scatter(const int* __restrict__ src,
                          const int* __restrict__ dst) {
    int e = blockIdx.x * 256 + threadIdx.x;
    if (e < NE) {
        int d = dst[e];
        int slot = atomicAdd(&g_cursor[d], 1);
        g_srcs[g_off[d] + slot] = src[e];
    }
}

// ---------------- projection GEMM: y = x @ W^T (packed f32x2) ----------------
// 64 nodes/block, 256 threads. Thread = (class-quad cp: 2 f32x2 pairs) x (4 nodes).
// Per k: 1 LDG.128 (W^T row slice, L1-hot 32KB) + amortized LDS.128 (x) + 8 FFMA2.
__global__ void __launch_bounds__(256) k_gemm(const float* __restrict__ x) {
    __shared__ float4 xs4[64 * (F / 4)];   // node-major [64][32] float4 = 32 KB
    int tid = threadIdx.x;
    int base = blockIdx.x * 64;

    // coalesced fill: per warp one node row (128B lines, conflict-free STS)
    for (int i = tid; i < 64 * 32; i += 256) {
        int n = i >> 5, kc = i & 31;
        int gn = base + n;
        float4 v = make_float4(0.f, 0.f, 0.f, 0.f);
        if (gn < NN) v = ((const float4*)x)[(size_t)gn * 32 + kc];
        xs4[n * 32 + kc] = v;
    }
    __syncthreads();

    int cp = tid & 15;          // class quad: classes 4cp..4cp+3
    int nl = tid >> 4;          // 0..15
    int n0 = nl * 4;            // 4 nodes per thread

    ull acc[2][4];              // [class-pair][node]
    #pragma unroll
    for (int j = 0; j < 2; j++)
        #pragma unroll
        for (int u = 0; u < 4; u++) acc[j][u] = 0ull;

    #pragma unroll 4
    for (int k4 = 0; k4 < F / 4; k4++) {
        float4 xq0 = xs4[(n0 + 0) * 32 + k4];
        float4 xq1 = xs4[(n0 + 1) * 32 + k4];
        float4 xq2 = xs4[(n0 + 2) * 32 + k4];
        float4 xq3 = xs4[(n0 + 3) * 32 + k4];
        const float* e0 = (const float*)&xq0;
        const float* e1 = (const float*)&xq1;
        const float* e2 = (const float*)&xq2;
        const float* e3 = (const float*)&xq3;
        #pragma unroll
        for (int j = 0; j < 4; j++) {
            float4 w = g_Wt4[(k4 * 4 + j) * 16 + cp];  // classes 4cp..4cp+3
            ull wlo = pack2(w.x, w.y);                 // reg-pair from LDG.128: free
            ull whi = pack2(w.z, w.w);
            ull d0 = pack2(e0[j], e0[j]);
            ull d1 = pack2(e1[j], e1[j]);
            ull d2 = pack2(e2[j], e2[j]);
            ull d3 = pack2(e3[j], e3[j]);
            acc[0][0] = ffma2(wlo, d0, acc[0][0]);
            acc[1][0] = ffma2(whi, d0, acc[1][0]);
            acc[0][1] = ffma2(wlo, d1, acc[0][1]);
            acc[1][1] = ffma2(whi, d1, acc[1][1]);
            acc[0][2] = ffma2(wlo, d2, acc[0][2]);
            acc[1][2] = ffma2(whi, d2, acc[1][2]);
            acc[0][3] = ffma2(wlo, d3, acc[0][3]);
            acc[1][3] = ffma2(whi, d3, acc[1][3]);
        }
    }

    #pragma unroll
    for (int u = 0; u < 4; u++) {
        int gn = base + n0 + u;
        if (gn < NN) {
            float4 o;
            unpack2(acc[0][u], o.x, o.y);
            unpack2(acc[1][u], o.z, o.w);
            g_y4[(size_t)gn * 16 + cp] = o;
        }
    }
}

// ---------------- gather + epilogue (unroll-4 for MLP) ----------------
// 16 threads per node (each owns a float4 of the 64-wide row). No atomics.
__global__ void __launch_bounds__(256) k_out(const float* __restrict__ bn,
                                             float* __restrict__ out) {
    int tid = threadIdx.x;
    int l  = tid & 15;
    int nl = tid >> 4;
    int v  = blockIdx.x * 16 + nl;     // 6250 * 16 == 100000

    float4 acc = g_y4[(size_t)v * 16 + l];   // self term

    int jb = g_off[v], je = g_off[v + 1];
    int j = jb;
    for (; j + 4 <= je; j += 4) {
        int s0 = g_srcs[j + 0];
        int s1 = g_srcs[j + 1];
        int s2 = g_srcs[j + 2];
        int s3 = g_srcs[j + 3];
        float4 t0 = g_y4[(size_t)s0 * 16 + l];
        float4 t1 = g_y4[(size_t)s1 * 16 + l];
        float4 t2 = g_y4[(size_t)s2 * 16 + l];
        float4 t3 = g_y4[(size_t)s3 * 16 + l];
        acc.x += t0.x + t1.x + t2.x + t3.x;
        acc.y += t0.y + t1.y + t2.y + t3.y;
        acc.z += t0.z + t1.z + t2.z + t3.z;
        acc.w += t0.w + t1.w + t2.w + t3.w;
    }
    for (; j < je; j++) {
        int s = g_srcs[j];
        float4 t = g_y4[(size_t)s * 16 + l];
        acc.x += t.x; acc.y += t.y; acc.z += t.z; acc.w += t.w;
    }

    float sc = 1.0f / (float)(je - jb + 1);
    float4 bb = ((const float4*)bn)[l];
    float4 o;
    o.x = acc.x * sc + bb.x;
    o.y = acc.y * sc + bb.y;
    o.z = acc.z * sc + bb.z;
    o.w = acc.w * sc + bb.w;
    ((float4*)out)[(size_t)v * 16 + l] = o;
}

extern "C" void kernel_launch(void* const* d_in, const int* in_sizes, int n_in,
                              void* d_out, int out_size) {
    const float* x    = (const float*)d_in[0];
    const int*   esrc = (const int*)d_in[1];
    const int*   edst = (const int*)d_in[2];
    const float* W    = (const float*)d_in[3];
    const float* bn   = (const float*)d_in[4];
    float* out = (float*)d_out;

    k_init<<<(NN + 255) / 256, 256>>>(W);
    k_count<<<(NE + 255) / 256, 256>>>(edst);
    k_scan1<<<NSCAN, SCAN_T>>>();
    k_scan2<<<1, 32>>>();
    k_scan3<<<NSCAN, SCAN_T>>>();
    k_scatter<<<(NE + 255) / 256, 256>>>(esrc, edst);
    k_gemm<<<(NN + 63) / 64, 256>>>(x);
    k_out<<<NN / 16, 256>>>(bn, out);
}

// round 5
// speedup vs baseline: 1.1617x; 1.0818x over previous
#include <cuda_runtime.h>
#include <cuda_bf16.h>
#include <cstdint>

#define NN 100000
#define NE 800000
#define F  128
#define C  64
#define SCAN_T 1024
#define NSCAN  98   // ceil(100000/1024)

typedef unsigned long long ull;

// ---- device scratch (no allocations allowed) ----
__device__ float4 g_y4[NN * (C / 4)];   // projected features y = x @ W^T (25.6 MB, L2-resident)
__device__ int    g_degi[NN];
__device__ int    g_cursor[NN];
__device__ int    g_off[NN + 1];
__device__ int    g_srcs[NE];           // CSR-by-dst neighbor lists
__device__ int    g_bsum[128];

// ---------------- init: zero counters ----------------
__global__ void k_init() {
    int i = blockIdx.x * 256 + threadIdx.x;
    if (i < NN) { g_degi[i] = 0; g_cursor[i] = 0; }
}

// ---------------- degree histogram (edges are int32) ----------------
__global__ void k_count(const int* __restrict__ dst) {
    int e = blockIdx.x * 256 + threadIdx.x;
    if (e < NE) atomicAdd(&g_degi[dst[e]], 1);
}

// ---------------- scan part 1: per-block exclusive scan ----------------
__global__ void k_scan1() {
    __shared__ int sh[SCAN_T];
    int tid = threadIdx.x;
    int i = blockIdx.x * SCAN_T + tid;
    int v = (i < NN) ? g_degi[i] : 0;
    sh[tid] = v;
    __syncthreads();
    for (int o = 1; o < SCAN_T; o <<= 1) {
        int t = (tid >= o) ? sh[tid - o] : 0;
        __syncthreads();
        sh[tid] += t;
        __syncthreads();
    }
    int incl = sh[tid];
    if (i < NN) g_off[i] = incl - v;
    if (tid == SCAN_T - 1) g_bsum[blockIdx.x] = incl;
}

// ---------------- scan part 2: add block prefix (serial scan folded in) ----------------
__global__ void k_scan3() {
    __shared__ int sb[NSCAN];
    __shared__ int pref;
    int tid = threadIdx.x;
    if (tid < NSCAN) sb[tid] = g_bsum[tid];
    __syncthreads();
    if (tid == 0) {
        int run = 0;
        #pragma unroll 7
        for (int i = 0; i < NSCAN; i++) {
            if (i == blockIdx.x) pref = run;
            run += sb[i];
        }
        if (blockIdx.x == 0) g_off[NN] = run;   // = NE
    }
    __syncthreads();
    int i = blockIdx.x * SCAN_T + tid;
    if (i < NN) g_off[i] += pref;
}

// ---------------- scatter edges into CSR slots ----------------
__global__ void k_scatter(const int* __restrict__ src,
                          const int* __restrict__ dst) {
    int e = blockIdx.x * 256 + threadIdx.x;
    if (e < NE) {
        int d = dst[e];
        int slot = atomicAdd(&g_cursor[d], 1);
        g_srcs[g_off[d] + slot] = src[e];
    }
}

// ============ tensor-core projection via mma.sync (HMMA, plain PTX ISA) ============
// Per CTA: M=128 nodes (8 warps x 16 rows), N=64 classes, K=128.
// bf16 2-term split: D = Ahi*Bhi + Alo*Bhi + Ahi*Blo  (fp32 accumulate).
// smem tiles k-contiguous, row stride 136 bf16 (272B) => conflict-free LDS.32
// fragment loads (bank = 4*(lane>>2) + (lane&3)).
#define AS 136                       // bf16 elements per row (stride)
#define ASB (AS * 2)                 // 272 bytes
#define SM_A_HI 0
#define SM_A_LO (128 * ASB)          // 34816
#define SM_B_HI (2 * 128 * ASB)      // 69632
#define SM_B_LO (2 * 128 * ASB + 64 * ASB)
#define SM_TOTAL (2 * 128 * ASB + 2 * 64 * ASB)   // 104448

__device__ __forceinline__ uint32_t pack_bf2(__nv_bfloat16 a, __nv_bfloat16 b) {
    return (uint32_t)__bfloat16_as_ushort(a) | ((uint32_t)__bfloat16_as_ushort(b) << 16);
}

__device__ __forceinline__ void mma16816(float* c, const uint32_t* a,
                                         uint32_t b0, uint32_t b1) {
    asm volatile(
        "mma.sync.aligned.m16n8k16.row.col.f32.bf16.bf16.f32 "
        "{%0,%1,%2,%3}, {%4,%5,%6,%7}, {%8,%9}, {%0,%1,%2,%3};"
        : "+f"(c[0]), "+f"(c[1]), "+f"(c[2]), "+f"(c[3])
        : "r"(a[0]), "r"(a[1]), "r"(a[2]), "r"(a[3]), "r"(b0), "r"(b1));
}

__global__ void __launch_bounds__(256, 2) k_gemm_mma(const float* __restrict__ x,
                                                     const float* __restrict__ W) {
    extern __shared__ char smem[];
    int tid = threadIdx.x;
    int base = blockIdx.x * 128;

    // ---- fill A (x tile 128x128, split hi/lo) ----
    for (int i = tid; i < 128 * 32; i += 256) {
        int row = i >> 5, kq = i & 31;        // kq: float4 index along K
        int gn = base + row;
        float4 v = make_float4(0.f, 0.f, 0.f, 0.f);
        if (gn < NN) v = ((const float4*)x)[(size_t)gn * 32 + kq];
        float e[4] = {v.x, v.y, v.z, v.w};
        __nv_bfloat16 h[4], l[4];
        #pragma unroll
        for (int j = 0; j < 4; j++) {
            h[j] = __float2bfloat16(e[j]);
            l[j] = __float2bfloat16(e[j] - __bfloat162float(h[j]));
        }
        uint32_t off = row * ASB + kq * 8;
        *(ull*)(smem + SM_A_HI + off) =
            (ull)pack_bf2(h[0], h[1]) | ((ull)pack_bf2(h[2], h[3]) << 32);
        *(ull*)(smem + SM_A_LO + off) =
            (ull)pack_bf2(l[0], l[1]) | ((ull)pack_bf2(l[2], l[3]) << 32);
    }
    // ---- fill B (W tile 64x128, split hi/lo). W[class][feat] is already K-major. ----
    for (int i = tid; i < 64 * 32; i += 256) {
        int row = i >> 5, kq = i & 31;
        float4 v = ((const float4*)W)[row * 32 + kq];
        float e[4] = {v.x, v.y, v.z, v.w};
        __nv_bfloat16 h[4], l[4];
        #pragma unroll
        for (int j = 0; j < 4; j++) {
            h[j] = __float2bfloat16(e[j]);
            l[j] = __float2bfloat16(e[j] - __bfloat162float(h[j]));
        }
        uint32_t off = row * ASB + kq * 8;
        *(ull*)(smem + SM_B_HI + off) =
            (ull)pack_bf2(h[0], h[1]) | ((ull)pack_bf2(h[2], h[3]) << 32);
        *(ull*)(smem + SM_B_LO + off) =
            (ull)pack_bf2(l[0], l[1]) | ((ull)pack_bf2(l[2], l[3]) << 32);
    }
    __syncthreads();

    int w  = tid >> 5;
    int l  = tid & 31;
    int g  = l >> 2;       // 0..7
    int tg = l & 3;        // 0..3
    int ar0 = w * 16 + g;  // this thread's A row (and +8)

    float c[8][4];
    #pragma unroll
    for (int nt = 0; nt < 8; nt++)
        #pragma unroll
        for (int j = 0; j < 4; j++) c[nt][j] = 0.f;

    #pragma unroll
    for (int ks = 0; ks < 8; ks++) {
        int k0 = ks * 16;
        uint32_t aoff = ar0 * ASB + (k0 + tg * 2) * 2;
        uint32_t ah[4], al[4];
        ah[0] = *(const uint32_t*)(smem + SM_A_HI + aoff);
        ah[1] = *(const uint32_t*)(smem + SM_A_HI + aoff + 8 * ASB);
        ah[2] = *(const uint32_t*)(smem + SM_A_HI + aoff + 16);
        ah[3] = *(const uint32_t*)(smem + SM_A_HI + aoff + 8 * ASB + 16);
        al[0] = *(const uint32_t*)(smem + SM_A_LO + aoff);
        al[1] = *(const uint32_t*)(smem + SM_A_LO + aoff + 8 * ASB);
        al[2] = *(const uint32_t*)(smem + SM_A_LO + aoff + 16);
        al[3] = *(const uint32_t*)(smem + SM_A_LO + aoff + 8 * ASB + 16);
        #pragma unroll
        for (int nt = 0; nt < 8; nt++) {
            uint32_t boff = (nt * 8 + g) * ASB + (k0 + tg * 2) * 2;
            uint32_t bh0 = *(const uint32_t*)(smem + SM_B_HI + boff);
            uint32_t bh1 = *(const uint32_t*)(smem + SM_B_HI + boff + 16);
            uint32_t bl0 = *(const uint32_t*)(smem + SM_B_LO + boff);
            uint32_t bl1 = *(const uint32_t*)(smem + SM_B_LO + boff + 16);
            mma16816(c[nt], ah, bh0, bh1);
            mma16816(c[nt], al, bh0, bh1);
            mma16816(c[nt], ah, bl0, bl1);
        }
    }

    // ---- write result fragments to g_y ----
    // Thread holds rows ar0 / ar0+8, cols nt*8 + tg*2 (+1).
    float2* yp = (float2*)g_y4;
    int gn0 = base + ar0;
    int gn1 = gn0 + 8;
    #pragma unroll
    for (int nt = 0; nt < 8; nt++) {
        if (gn0 < NN) yp[(size_t)gn0 * 32 + nt * 4 + tg] = make_float2(c[nt][0], c[nt][1]);
        if (gn1 < NN) yp[(size_t)gn1 * 32 + nt * 4 + tg] = make_float2(c[nt][2], c[nt][3]);
    }
}

// ---------------- gather + epilogue (unroll-4 for MLP) ----------------
__global__ void __launch_bounds__(256) k_out(const float* __restrict__ bn,
                                             float* __restrict__ out) {
    int tid = threadIdx.x;
    int l  = tid & 15;
    int nl = tid >> 4;
    int v  = blockIdx.x * 16 + nl;     // 6250 * 16 == 100000

    float4 acc = g_y4[(size_t)v * 16 + l];   // self term

    int jb = g_off[v], je = g_off[v + 1];
    int j = jb;
    for (; j + 4 <= je; j += 4) {
        int s0 = g_srcs[j + 0];
        int s1 = g_srcs[j + 1];
        int s2 = g_srcs[j + 2];
        int s3 = g_srcs[j + 3];
        float4 t0 = g_y4[(size_t)s0 * 16 + l];
        float4 t1 = g_y4[(size_t)s1 * 16 + l];
        float4 t2 = g_y4[(size_t)s2 * 16 + l];
        float4 t3 = g_y4[(size_t)s3 * 16 + l];
        acc.x += t0.x + t1.x + t2.x + t3.x;
        acc.y += t0.y + t1.y + t2.y + t3.y;
        acc.z += t0.z + t1.z + t2.z + t3.z;
        acc.w += t0.w + t1.w + t2.w + t3.w;
    }
    for (; j < je; j++) {
        int s = g_srcs[j];
        float4 t = g_y4[(size_t)s * 16 + l];
        acc.x += t.x; acc.y += t.y; acc.z += t.z; acc.w += t.w;
    }

    float sc = 1.0f / (float)(je - jb + 1);
    float4 bb = ((const float4*)bn)[l];
    float4 o;
    o.x = acc.x * sc + bb.x;
    o.y = acc.y * sc + bb.y;
    o.z = acc.z * sc + bb.z;
    o.w = acc.w * sc + bb.w;
    ((float4*)out)[(size_t)v * 16 + l] = o;
}

extern "C" void kernel_launch(void* const* d_in, const int* in_sizes, int n_in,
                              void* d_out, int out_size) {
    const float* x    = (const float*)d_in[0];
    const int*   esrc = (const int*)d_in[1];
    const int*   edst = (const int*)d_in[2];
    const float* W    = (const float*)d_in[3];
    const float* bn   = (const float*)d_in[4];
    float* out = (float*)d_out;

    cudaFuncSetAttribute(k_gemm_mma, cudaFuncAttributeMaxDynamicSharedMemorySize, SM_TOTAL);

    k_init<<<(NN + 255) / 256, 256>>>();
    k_count<<<(NE + 255) / 256, 256>>>(edst);
    k_scan1<<<NSCAN, SCAN_T>>>();
    k_scan3<<<NSCAN, SCAN_T>>>();
    k_scatter<<<(NE + 255) / 256, 256>>>(esrc, edst);
    k_gemm_mma<<<(NN + 127) / 128, 256, SM_TOTAL>>>(x, W);
    k_out<<<NN / 16, 256>>>(bn, out);
}

// round 6
// speedup vs baseline: 1.3077x; 1.1257x over previous
#include <cuda_runtime.h>
#include <cuda_bf16.h>
#include <cstdint>

#define NN 100000
#define NE 800000
#define F  128
#define C  64
#define SCAN_T 1024
#define NSCAN  98   // ceil(100000/1024)

typedef unsigned long long ull;

// ---- device scratch (no allocations allowed) ----
__device__ float4 g_y4[NN * (C / 4)];   // projected features y = x @ W^T (25.6 MB, L2-resident)
__device__ int    g_cnt[2 * NN];        // [0,NN): degree, [NN,2NN): scatter cursor
__device__ int    g_off[NN + 1];
__device__ int    g_srcs[NE];           // CSR-by-dst neighbor lists
__device__ int    g_bsum[128];

// ---------------- degree histogram (edges are int32) ----------------
__global__ void k_count(const int* __restrict__ dst) {
    int e = blockIdx.x * 256 + threadIdx.x;
    if (e < NE) atomicAdd(&g_cnt[dst[e]], 1);
}

// ---------------- scan part 1: per-block exclusive scan (shfl) ----------------
__global__ void k_scan1() {
    __shared__ int ws[32];
    int tid = threadIdx.x;
    int i = blockIdx.x * SCAN_T + tid;
    int v = (i < NN) ? g_cnt[i] : 0;
    int incl = v;
    #pragma unroll
    for (int o = 1; o < 32; o <<= 1) {
        int t = __shfl_up_sync(~0u, incl, o);
        if ((tid & 31) >= o) incl += t;
    }
    if ((tid & 31) == 31) ws[tid >> 5] = incl;
    __syncthreads();
    if (tid < 32) {
        int s = ws[tid];
        int sc = s;
        #pragma unroll
        for (int o = 1; o < 32; o <<= 1) {
            int t = __shfl_up_sync(~0u, sc, o);
            if (tid >= o) sc += t;
        }
        ws[tid] = sc - s;   // exclusive warp offset
    }
    __syncthreads();
    incl += ws[tid >> 5];
    if (i < NN) g_off[i] = incl - v;
    if (tid == SCAN_T - 1) g_bsum[blockIdx.x] = incl;
}

// ---------------- scan part 2: 1-warp exclusive scan of 98 block sums ----------------
__global__ void k_scan2() {
    int lane = threadIdx.x;   // 32 threads
    int carry = 0;
    #pragma unroll
    for (int b = 0; b < NSCAN; b += 32) {
        int idx = b + lane;
        int v = (idx < NSCAN) ? g_bsum[idx] : 0;
        int inc = v;
        #pragma unroll
        for (int o = 1; o < 32; o <<= 1) {
            int t = __shfl_up_sync(~0u, inc, o);
            if (lane >= o) inc += t;
        }
        if (idx < NSCAN) g_bsum[idx] = carry + inc - v;   // exclusive prefix
        carry += __shfl_sync(~0u, inc, 31);
    }
    if (lane == 0) g_off[NN] = carry;   // = NE
}

// ---------------- scan part 3: add block prefix ----------------
__global__ void k_scan3() {
    int i = blockIdx.x * SCAN_T + threadIdx.x;
    if (i < NN) g_off[i] += g_bsum[blockIdx.x];
}

// ---------------- scatter edges into CSR slots ----------------
__global__ void k_scatter(const int* __restrict__ src,
                          const int* __restrict__ dst) {
    int e = blockIdx.x * 256 + threadIdx.x;
    if (e < NE) {
        int d = dst[e];
        int slot = atomicAdd(&g_cnt[NN + d], 1);
        g_srcs[g_off[d] + slot] = src[e];
    }
}

// ============ tensor-core projection via mma.sync (HMMA, plain PTX ISA) ============
// Per CTA: M=128 nodes (8 warps x 16 rows), N=64 classes, K=128.
// bf16 2-term split: D = Ahi*Bhi + Alo*Bhi + Ahi*Blo  (fp32 accumulate).
#define AS 136                       // bf16 elements per row (stride)
#define ASB (AS * 2)                 // 272 bytes
#define SM_A_HI 0
#define SM_A_LO (128 * ASB)
#define SM_B_HI (2 * 128 * ASB)
#define SM_B_LO (2 * 128 * ASB + 64 * ASB)
#define SM_TOTAL (2 * 128 * ASB + 2 * 64 * ASB)   // 104448

__device__ __forceinline__ uint32_t pack_bf2(__nv_bfloat16 a, __nv_bfloat16 b) {
    return (uint32_t)__bfloat16_as_ushort(a) | ((uint32_t)__bfloat16_as_ushort(b) << 16);
}

__device__ __forceinline__ void mma16816(float* c, const uint32_t* a,
                                         uint32_t b0, uint32_t b1) {
    asm volatile(
        "mma.sync.aligned.m16n8k16.row.col.f32.bf16.bf16.f32 "
        "{%0,%1,%2,%3}, {%4,%5,%6,%7}, {%8,%9}, {%0,%1,%2,%3};"
        : "+f"(c[0]), "+f"(c[1]), "+f"(c[2]), "+f"(c[3])
        : "r"(a[0]), "r"(a[1]), "r"(a[2]), "r"(a[3]), "r"(b0), "r"(b1));
}

__global__ void __launch_bounds__(256, 2) k_gemm_mma(const float* __restrict__ x,
                                                     const float* __restrict__ W) {
    extern __shared__ char smem[];
    int tid = threadIdx.x;
    int base = blockIdx.x * 128;

    // ---- fill A (x tile 128x128, split hi/lo) ----
    for (int i = tid; i < 128 * 32; i += 256) {
        int row = i >> 5, kq = i & 31;
        int gn = base + row;
        float4 v = make_float4(0.f, 0.f, 0.f, 0.f);
        if (gn < NN) v = ((const float4*)x)[(size_t)gn * 32 + kq];
        float e[4] = {v.x, v.y, v.z, v.w};
        __nv_bfloat16 h[4], l[4];
        #pragma unroll
        for (int j = 0; j < 4; j++) {
            h[j] = __float2bfloat16(e[j]);
            l[j] = __float2bfloat16(e[j] - __bfloat162float(h[j]));
        }
        uint32_t off = row * ASB + kq * 8;
        *(ull*)(smem + SM_A_HI + off) =
            (ull)pack_bf2(h[0], h[1]) | ((ull)pack_bf2(h[2], h[3]) << 32);
        *(ull*)(smem + SM_A_LO + off) =
            (ull)pack_bf2(l[0], l[1]) | ((ull)pack_bf2(l[2], l[3]) << 32);
    }
    // ---- fill B (W tile 64x128, split hi/lo). W[class][feat] is K-major. ----
    for (int i = tid; i < 64 * 32; i += 256) {
        int row = i >> 5, kq = i & 31;
        float4 v = ((const float4*)W)[row * 32 + kq];
        float e[4] = {v.x, v.y, v.z, v.w};
        __nv_bfloat16 h[4], l[4];
        #pragma unroll
        for (int j = 0; j < 4; j++) {
            h[j] = __float2bfloat16(e[j]);
            l[j] = __float2bfloat16(e[j] - __bfloat162float(h[j]));
        }
        uint32_t off = row * ASB + kq * 8;
        *(ull*)(smem + SM_B_HI + off) =
            (ull)pack_bf2(h[0], h[1]) | ((ull)pack_bf2(h[2], h[3]) << 32);
        *(ull*)(smem + SM_B_LO + off) =
            (ull)pack_bf2(l[0], l[1]) | ((ull)pack_bf2(l[2], l[3]) << 32);
    }
    __syncthreads();

    int w  = tid >> 5;
    int l  = tid & 31;
    int g  = l >> 2;
    int tg = l & 3;
    int ar0 = w * 16 + g;

    float c[8][4];
    #pragma unroll
    for (int nt = 0; nt < 8; nt++)
        #pragma unroll
        for (int j = 0; j < 4; j++) c[nt][j] = 0.f;

    #pragma unroll
    for (int ks = 0; ks < 8; ks++) {
        int k0 = ks * 16;
        uint32_t aoff = ar0 * ASB + (k0 + tg * 2) * 2;
        uint32_t ah[4], al[4];
        ah[0] = *(const uint32_t*)(smem + SM_A_HI + aoff);
        ah[1] = *(const uint32_t*)(smem + SM_A_HI + aoff + 8 * ASB);
        ah[2] = *(const uint32_t*)(smem + SM_A_HI + aoff + 16);
        ah[3] = *(const uint32_t*)(smem + SM_A_HI + aoff + 8 * ASB + 16);
        al[0] = *(const uint32_t*)(smem + SM_A_LO + aoff);
        al[1] = *(const uint32_t*)(smem + SM_A_LO + aoff + 8 * ASB);
        al[2] = *(const uint32_t*)(smem + SM_A_LO + aoff + 16);
        al[3] = *(const uint32_t*)(smem + SM_A_LO + aoff + 8 * ASB + 16);
        #pragma unroll
        for (int nt = 0; nt < 8; nt++) {
            uint32_t boff = (nt * 8 + g) * ASB + (k0 + tg * 2) * 2;
            uint32_t bh0 = *(const uint32_t*)(smem + SM_B_HI + boff);
            uint32_t bh1 = *(const uint32_t*)(smem + SM_B_HI + boff + 16);
            uint32_t bl0 = *(const uint32_t*)(smem + SM_B_LO + boff);
            uint32_t bl1 = *(const uint32_t*)(smem + SM_B_LO + boff + 16);
            mma16816(c[nt], ah, bh0, bh1);
            mma16816(c[nt], al, bh0, bh1);
            mma16816(c[nt], ah, bl0, bl1);
        }
    }

    float2* yp = (float2*)g_y4;
    int gn0 = base + ar0;
    int gn1 = gn0 + 8;
    #pragma unroll
    for (int nt = 0; nt < 8; nt++) {
        if (gn0 < NN) yp[(size_t)gn0 * 32 + nt * 4 + tg] = make_float2(c[nt][0], c[nt][1]);
        if (gn1 < NN) yp[(size_t)gn1 * 32 + nt * 4 + tg] = make_float2(c[nt][2], c[nt][3]);
    }
}

// ---------------- gather + epilogue (unroll-4 for MLP) ----------------
__global__ void __launch_bounds__(256) k_out(const float* __restrict__ bn,
                                             float* __restrict__ out) {
    int tid = threadIdx.x;
    int l  = tid & 15;
    int nl = tid >> 4;
    int v  = blockIdx.x * 16 + nl;     // 6250 * 16 == 100000

    float4 acc = g_y4[(size_t)v * 16 + l];   // self term

    int jb = g_off[v], je = g_off[v + 1];
    int j = jb;
    for (; j + 4 <= je; j += 4) {
        int s0 = g_srcs[j + 0];
        int s1 = g_srcs[j + 1];
        int s2 = g_srcs[j + 2];
        int s3 = g_srcs[j + 3];
        float4 t0 = g_y4[(size_t)s0 * 16 + l];
        float4 t1 = g_y4[(size_t)s1 * 16 + l];
        float4 t2 = g_y4[(size_t)s2 * 16 + l];
        float4 t3 = g_y4[(size_t)s3 * 16 + l];
        acc.x += t0.x + t1.x + t2.x + t3.x;
        acc.y += t0.y + t1.y + t2.y + t3.y;
        acc.z += t0.z + t1.z + t2.z + t3.z;
        acc.w += t0.w + t1.w + t2.w + t3.w;
    }
    for (; j < je; j++) {
        int s = g_srcs[j];
        float4 t = g_y4[(size_t)s * 16 + l];
        acc.x += t.x; acc.y += t.y; acc.z += t.z; acc.w += t.w;
    }

    float sc = 1.0f / (float)(je - jb + 1);
    float4 bb = ((const float4*)bn)[l];
    float4 o;
    o.x = acc.x * sc + bb.x;
    o.y = acc.y * sc + bb.y;
    o.z = acc.z * sc + bb.z;
    o.w = acc.w * sc + bb.w;
    ((float4*)out)[(size_t)v * 16 + l] = o;
}

extern "C" void kernel_launch(void* const* d_in, const int* in_sizes, int n_in,
                              void* d_out, int out_size) {
    const float* x    = (const float*)d_in[0];
    const int*   esrc = (const int*)d_in[1];
    const int*   edst = (const int*)d_in[2];
    const float* W    = (const float*)d_in[3];
    const float* bn   = (const float*)d_in[4];
    float* out = (float*)d_out;

    static cudaStream_t s1 = nullptr;
    static cudaEvent_t ev_root = nullptr, ev_gemm = nullptr;
    if (!s1) {
        cudaStreamCreateWithFlags(&s1, cudaStreamNonBlocking);
        cudaEventCreateWithFlags(&ev_root, cudaEventDisableTiming);
        cudaEventCreateWithFlags(&ev_gemm, cudaEventDisableTiming);
        cudaFuncSetAttribute(k_gemm_mma, cudaFuncAttributeMaxDynamicSharedMemorySize, SM_TOTAL);
    }

    void* cnt_ptr = nullptr;
    cudaGetSymbolAddress(&cnt_ptr, g_cnt);

    // fork: GEMM on side stream, CSR build on main stream
    cudaEventRecord(ev_root, 0);
    cudaStreamWaitEvent(s1, ev_root, 0);
    k_gemm_mma<<<(NN + 127) / 128, 256, SM_TOTAL, s1>>>(x, W);
    cudaEventRecord(ev_gemm, s1);

    cudaMemsetAsync(cnt_ptr, 0, 2 * NN * sizeof(int), 0);
    k_count<<<(NE + 255) / 256, 256>>>(edst);
    k_scan1<<<NSCAN, SCAN_T>>>();
    k_scan2<<<1, 32>>>();
    k_scan3<<<NSCAN, SCAN_T>>>();
    k_scatter<<<(NE + 255) / 256, 256>>>(esrc, edst);

    // join: k_out needs both g_y (gemm) and CSR
    cudaStreamWaitEvent(0, ev_gemm, 0);
    k_out<<<NN / 16, 256>>>(bn, out);
}